// round 10
// baseline (speedup 1.0000x reference)
#include <cuda_runtime.h>
#include <cstdint>

// CFConv: y[idx_i[e]] += x[idx_j[e]] * Wij[e]  (F=64), idx_i sorted.
// E ~ 1.25M, N = 50000.
//
// R6: R4 grid (best measured) + full 32-bit offset arithmetic (all offsets
// < 2^31) to cut IMAD.WIDE register pairs, + launch_bounds(256,6) -> 42-reg
// clamp -> 6 CTAs/SM (75% occ cap). Goal: more DRAM loads in flight; traffic
// is already at the compulsory floor (~366 MB), only achieved-BW remains.

#define F_DIM 64
#define WPB   8                   // warps per block -> 256 threads
#define THREADS (32 * WPB)
#define CHUNK 64                  // edges per warp

__device__ __forceinline__ void flush_acc(float* __restrict__ y, int cur, int fo,
                                          float2& acc) {
    float* p = y + cur * F_DIM + fo;       // cur*64+fo < 3.2M, int ok
    atomicAdd(p + 0, acc.x);
    atomicAdd(p + 1, acc.y);
    acc.x = 0.f; acc.y = 0.f;
}

__global__ __launch_bounds__(THREADS, 6) void cfconv_kernel(
    const float* __restrict__ x,
    const float* __restrict__ Wij,
    const int* __restrict__ idx_i,
    const int* __restrict__ idx_j,
    float* __restrict__ y,
    int E) {
    // Inline idx dtype detection: values < 50000, so int64 (LE) => odd 32-bit
    // words all zero. Broadcast loads, L2-hit, uniform result.
    int all_zero = 1;
    #pragma unroll
    for (int k = 1; k <= 31; k += 2) all_zero &= (__ldg(idx_j + k) == 0);
    const int stride = all_zero ? 2 : 1;

    const int lane = threadIdx.x & 31;
    const int warp = blockIdx.x * WPB + (threadIdx.x >> 5);
    int e0 = warp * CHUNK;
    if (e0 >= E) return;
    int e1 = e0 + CHUNK;
    if (e1 > E) e1 = E;

    const int fo = lane * 2;
    // float2-typed bases; all offsets below are int float2-offsets (< 2^31).
    const float2* __restrict__ wb = (const float2*)(Wij + fo);
    const float2* __restrict__ xb = (const float2*)(x + fo);

    int cur = __ldg(idx_i + e0 * stride);
    float2 acc = make_float2(0.f, 0.f);

    int base = e0;

    // Prefetch first index batch (coalesced: lane l loads edge base+l).
    int my_i = 0, my_j = 0;
    if (base + 32 <= e1) {
        my_i = __ldg(idx_i + (base + lane) * stride);
        my_j = __ldg(idx_j + (base + lane) * stride);
    }

    for (; base + 32 <= e1; base += 32) {
        int nx_i = 0, nx_j = 0;
        if (base + 64 <= e1) {
            nx_i = __ldg(idx_i + (base + 32 + lane) * stride);
            nx_j = __ldg(idx_j + (base + 32 + lane) * stride);
        }

        #pragma unroll
        for (int k0 = 0; k0 < 32; k0 += 4) {
            int j0 = __shfl_sync(0xFFFFFFFFu, my_j, k0 + 0);
            int j1 = __shfl_sync(0xFFFFFFFFu, my_j, k0 + 1);
            int j2 = __shfl_sync(0xFFFFFFFFu, my_j, k0 + 2);
            int j3 = __shfl_sync(0xFFFFFFFFu, my_j, k0 + 3);

            const int eb = (base + k0) * 32;   // float2 offset of edge row
            // Issue all 8 loads before consuming anything (MLP ~ 8).
            float2 w0 = __ldcs(wb + eb + 0 * 32);
            float2 w1 = __ldcs(wb + eb + 1 * 32);
            float2 w2 = __ldcs(wb + eb + 2 * 32);
            float2 w3 = __ldcs(wb + eb + 3 * 32);
            float2 x0 = __ldg(xb + j0 * 32);
            float2 x1 = __ldg(xb + j1 * 32);
            float2 x2 = __ldg(xb + j2 * 32);
            float2 x3 = __ldg(xb + j3 * 32);

            int i0 = __shfl_sync(0xFFFFFFFFu, my_i, k0 + 0);
            int i1 = __shfl_sync(0xFFFFFFFFu, my_i, k0 + 1);
            int i2 = __shfl_sync(0xFFFFFFFFu, my_i, k0 + 2);
            int i3 = __shfl_sync(0xFFFFFFFFu, my_i, k0 + 3);

            if (i0 != cur) { flush_acc(y, cur, fo, acc); cur = i0; }
            acc.x += x0.x * w0.x; acc.y += x0.y * w0.y;

            if (i1 != cur) { flush_acc(y, cur, fo, acc); cur = i1; }
            acc.x += x1.x * w1.x; acc.y += x1.y * w1.y;

            if (i2 != cur) { flush_acc(y, cur, fo, acc); cur = i2; }
            acc.x += x2.x * w2.x; acc.y += x2.y * w2.y;

            if (i3 != cur) { flush_acc(y, cur, fo, acc); cur = i3; }
            acc.x += x3.x * w3.x; acc.y += x3.y * w3.y;
        }

        my_i = nx_i;
        my_j = nx_j;
    }

    // Scalar tail (< 32 edges).
    for (; base < e1; ++base) {
        int i = __ldg(idx_i + base * stride);
        int j = __ldg(idx_j + base * stride);
        float2 w  = __ldcs(wb + base * 32);
        float2 xv = __ldg(xb + j * 32);
        if (i != cur) { flush_acc(y, cur, fo, acc); cur = i; }
        acc.x += xv.x * w.x; acc.y += xv.y * w.y;
    }

    flush_acc(y, cur, fo, acc);
}

extern "C" void kernel_launch(void* const* d_in, const int* in_sizes, int n_in,
                              void* d_out, int out_size) {
    const float* x   = (const float*)d_in[0];
    const float* Wij = (const float*)d_in[1];
    const int*   idx_i = (const int*)d_in[2];
    const int*   idx_j = (const int*)d_in[3];
    float* y = (float*)d_out;

    const int E = in_sizes[2];

    cudaMemsetAsync(d_out, 0, (size_t)out_size * sizeof(float));

    const int warps = (E + CHUNK - 1) / CHUNK;
    const int blocks = (warps + WPB - 1) / WPB;
    cfconv_kernel<<<blocks, THREADS>>>(x, Wij, idx_i, idx_j, y, E);
}